// round 14
// baseline (speedup 1.0000x reference)
#include <cuda_runtime.h>
#include <cstdint>

#define DIN   512
#define DOUT  4096
#define CAP   96          // max stored nonzeros per column

#define RB    64          // batch rows per GEMM CTA (2 rows per lane)
#define WARPS 16
#define CPW   64          // columns per warp
#define XPITCH 66         // x-tile pitch (even -> aligned float2, conflict-free)
#define OSP   9           // out-staging pitch

// ---------------- device scratch (static: allocation-free) ----------------
// g_list entries: {byte offset idx*XPITCH*4, fp32 bits of W*mask}, padded to
// even count with exact {0, 0.0f} (adding 0.0 is fp32-exact).
__device__ __align__(16) int2  g_list[DOUT * CAP];
__device__            int      g_nnz[DOUT];
__device__ __align__(16) float g_boost[DOUT];

// ---------------- kernel 1: compact sparse lists + boost ----------------
__global__ void k_prep(const float* __restrict__ W, const float* __restrict__ M,
                       const float* __restrict__ duty, const int* __restrict__ kptr) {
    int gt = blockIdx.x * blockDim.x + threadIdx.x;
    if (gt < DOUT) {
        float target = (float)(*kptr) / (float)DOUT;
        g_boost[gt] = expf(0.5f * (target - duty[gt]));
    }
    int j    = blockIdx.x * (blockDim.x >> 5) + (threadIdx.x >> 5);
    int lane = threadIdx.x & 31;
    if (j >= DOUT) return;
    const float* Wr = W + (size_t)j * DIN;
    const float* Mr = M + (size_t)j * DIN;
    int base = 0;
    for (int c = 0; c < DIN / 32; ++c) {
        int i = c * 32 + lane;
        float w = Wr[i] * Mr[i];                 // mask is exactly 0.0 or 1.0
        bool nz = (w != 0.0f);
        unsigned bal = __ballot_sync(0xffffffffu, nz);
        int pos = base + __popc(bal & ((1u << lane) - 1u));
        if (nz && pos < CAP)
            g_list[j * CAP + pos] = make_int2(i * XPITCH * 4, __float_as_int(w));
        base += __popc(bal);
    }
    if (lane == 0) {
        int n = (base < CAP) ? base : CAP;
        if ((n & 1) && n < CAP) g_list[j * CAP + n] = make_int2(0, 0); // exact pad
        g_nnz[j] = n;
    }
}

// ---------------- kernel 2: sparse gather GEMM (fp32 bit-exact, R9 best) ----
__global__ void __launch_bounds__(32 * WARPS, 1)
k_gemm(const float* __restrict__ x, const float* __restrict__ bias,
       float* __restrict__ yout) {
    extern __shared__ float sm[];
    float* xs  = sm;                       // [DIN][XPITCH] transposed x tile
    float* os  = sm + DIN * XPITCH;        // [WARPS][RB][OSP] out staging
    int4*  stg = (int4*)(os + WARPS * RB * OSP); // [WARPS][2][32] entry pairs
    int tid  = threadIdx.x;
    int w    = tid >> 5;
    int lane = tid & 31;
    int rowbase = blockIdx.x * RB;

    const float4* x4 = (const float4*)(x + (size_t)rowbase * DIN);
    for (int t = tid; t < RB * (DIN / 4); t += blockDim.x) {
        int r  = t >> 7;
        int i4 = t & 127;
        float4 v = x4[(size_t)r * (DIN / 4) + i4];
        int ib = i4 * 4;
        xs[(ib + 0) * XPITCH + r] = v.x;
        xs[(ib + 1) * XPITCH + r] = v.y;
        xs[(ib + 2) * XPITCH + r] = v.z;
        xs[(ib + 3) * XPITCH + r] = v.w;
    }
    __syncthreads();

    float* osw  = os + w * (RB * OSP);
    int jwarp   = blockIdx.y * (WARPS * CPW) + w * CPW;
    const char* xbase = (const char*)xs + lane * 8;
    int2* stgw = (int2*)(stg + w * 64);

    const int2* L;
    L = &g_list[(size_t)jwarp * CAP];
    int2 rA = __ldg(L + lane), rB = __ldg(L + 32 + lane);
    int n_cur = __ldg(&g_nnz[jwarp]);
    stgw[lane] = rA; stgw[32 + lane] = rB;
    L = &g_list[(size_t)(jwarp + 1) * CAP];
    rA = __ldg(L + lane); rB = __ldg(L + 32 + lane);
    int n_nxt = __ldg(&g_nnz[jwarp + 1]);
    __syncwarp();

    for (int ci = 0; ci < CPW; ++ci) {
        int j = jwarp + ci;
        if (ci + 1 < CPW) {
            int2* sb = stgw + ((ci + 1) & 1) * 64;
            sb[lane] = rA; sb[32 + lane] = rB;
        }
        int n_pf = 0;
        if (ci + 2 < CPW) {
            L = &g_list[(size_t)(jwarp + ci + 2) * CAP];
            rA = __ldg(L + lane); rB = __ldg(L + 32 + lane);
            n_pf = __ldg(&g_nnz[jwarp + ci + 2]);
        }

        const int4* sb4 = (const int4*)(stgw + (ci & 1) * 64);
        int nc = (n_cur < 64) ? n_cur : 64;
        int npairs = (nc + 1) >> 1;
        float acc0 = 0.f, acc1 = 0.f;
        #pragma unroll 4
        for (int p = 0; p < npairs; ++p) {
            int4 q = sb4[p];
            float2 xv0 = *(const float2*)(xbase + q.x);
            float2 xv1 = *(const float2*)(xbase + q.z);
            float v0 = __int_as_float(q.y);
            float v1 = __int_as_float(q.w);
            acc0 = fmaf(xv0.x, v0, acc0);
            acc1 = fmaf(xv0.y, v0, acc1);
            acc0 = fmaf(xv1.x, v1, acc0);
            acc1 = fmaf(xv1.y, v1, acc1);
        }
        if (n_cur > 64) {
            for (int e = 64; e < n_cur; ++e) {
                int2 pe = __ldg(&g_list[(size_t)j * CAP + e]);
                float v = __int_as_float(pe.y);
                float2 xv = *(const float2*)(xbase + pe.x);
                acc0 = fmaf(xv.x, v, acc0);
                acc1 = fmaf(xv.y, v, acc1);
            }
        }
        float bj = __ldg(&bias[j]);
        int cc = ci & 7;
        osw[(2 * lane)     * OSP + cc] = acc0 + bj;
        osw[(2 * lane + 1) * OSP + cc] = acc1 + bj;

        n_cur = n_nxt; n_nxt = n_pf;

        if (cc == 7) {
            __syncwarp();
            int j0 = jwarp + (ci & ~7);
            #pragma unroll
            for (int q = 0; q < 4; ++q) {
                int chunk = q * 32 + lane;
                int row   = chunk >> 1;
                int c0    = (chunk & 1) * 4;
                float4 v;
                v.x = osw[row * OSP + c0 + 0];
                v.y = osw[row * OSP + c0 + 1];
                v.z = osw[row * OSP + c0 + 2];
                v.w = osw[row * OSP + c0 + 3];
                *(float4*)&yout[(size_t)(rowbase + row) * DOUT + j0 + c0] = v;
            }
        }
        __syncwarp();
    }
}

// ---------------- kernel 3: select = 10-bit hist + exact 22-bit bisection ---
__global__ void __launch_bounds__(512)
k_select(float* __restrict__ y, const int* __restrict__ kptr) {
    __shared__ unsigned hist[1024];
    __shared__ unsigned ssum[1024];
    __shared__ unsigned warptot[16];
    __shared__ unsigned cand[3072];
    __shared__ unsigned s_cnt, s_bin, s_need, s_thr, s_ovf, s_c;

    int tid  = threadIdx.x;
    int w    = tid >> 5;
    int lane = tid & 31;
    size_t rowoff = (size_t)blockIdx.x * DOUT;
    const float4* y4 = (const float4*)(y + rowoff);
    const float4* b4 = (const float4*)g_boost;

    float    vreg[8];
    unsigned kreg[8];
    #pragma unroll
    for (int q = 0; q < 2; ++q) {
        int t = tid + 512 * q;
        float4 v  = y4[t];
        float4 bo = b4[t];
        float bv[4] = { v.x * bo.x, v.y * bo.y, v.z * bo.z, v.w * bo.w };
        vreg[q * 4 + 0] = v.x; vreg[q * 4 + 1] = v.y;
        vreg[q * 4 + 2] = v.z; vreg[q * 4 + 3] = v.w;
        #pragma unroll
        for (int e = 0; e < 4; ++e) {
            unsigned u = __float_as_uint(bv[e]);
            kreg[q * 4 + e] = (u & 0x80000000u) ? ~u : (u | 0x80000000u);
        }
    }
    hist[tid] = 0u; hist[tid + 512] = 0u;
    if (tid == 0) { s_cnt = 0u; s_ovf = 0u; }
    __syncthreads();

    // 10-bit histogram, match_any-aggregated (skew-safe)
    #pragma unroll
    for (int e = 0; e < 8; ++e) {
        int bin = kreg[e] >> 22;
        unsigned mm = __match_any_sync(0xffffffffu, bin);
        if (lane == (__ffs(mm) - 1)) atomicAdd(&hist[bin], __popc(mm));
    }
    __syncthreads();

    // suffix scan over 1024 bins (2 per thread): S[b] = #keys with (key>>22)>=b
    unsigned h0 = hist[2 * tid], h1 = hist[2 * tid + 1];
    unsigned p  = h0 + h1;
    unsigned inc = p;
    #pragma unroll
    for (int off = 1; off < 32; off <<= 1) {
        unsigned o = __shfl_down_sync(0xffffffffu, inc, off);
        if (lane + off < 32) inc += o;
    }
    if (lane == 0) warptot[w] = inc;
    __syncthreads();
    unsigned above = 0;
    #pragma unroll
    for (int ww = 0; ww < 16; ++ww) if (ww > w) above += warptot[ww];
    unsigned strictAfter = above + (inc - p);
    ssum[2 * tid]     = strictAfter + p;
    ssum[2 * tid + 1] = strictAfter + h1;
    __syncthreads();

    unsigned kk = (unsigned)(*kptr);
    #pragma unroll
    for (int q = 0; q < 2; ++q) {
        int bb = 2 * tid + q;
        unsigned S = ssum[bb];
        unsigned Snext = (bb == 1023) ? 0u : ssum[bb + 1];
        if (S >= kk && Snext < kk) { s_bin = (unsigned)bb; s_need = kk - Snext; }
    }
    __syncthreads();
    unsigned b = s_bin, need = s_need;

    // collect boundary-bin candidates
    #pragma unroll
    for (int e = 0; e < 8; ++e) {
        if ((kreg[e] >> 22) == b) {
            unsigned pos = atomicAdd(&s_cnt, 1u);
            if (pos < 3072u) cand[pos] = kreg[e]; else s_ovf = 1u;
        }
    }
    __syncthreads();

    if (!s_ovf) {
        if (w == 0) {                     // warp 0: exact 22-bit bisection
            unsigned cnt = s_cnt;
            unsigned pref = b << 22;
            for (int bit = 21; bit >= 0; --bit) {
                unsigned trial = pref | (1u << bit);
                unsigned c = 0;
                for (unsigned i = lane; i < cnt; i += 32) c += (cand[i] >= trial);
                #pragma unroll
                for (int off = 16; off > 0; off >>= 1)
                    c += __shfl_down_sync(0xffffffffu, c, off);
                c = __shfl_sync(0xffffffffu, c, 0);
                if (c >= need) pref = trial;
            }
            if (lane == 0) s_thr = pref;
        }
    } else {                              // exact fallback (never in practice)
        unsigned pref = b << 22;
        for (int bit = 21; bit >= 0; --bit) {
            if (tid == 0) s_c = 0u;
            __syncthreads();
            unsigned trial = pref | (1u << bit);
            unsigned c = 0;
            #pragma unroll
            for (int e = 0; e < 8; ++e)
                c += ((kreg[e] >> 22) == b && kreg[e] >= trial);
            #pragma unroll
            for (int off = 16; off > 0; off >>= 1)
                c += __shfl_down_sync(0xffffffffu, c, off);
            if (lane == 0) atomicAdd(&s_c, c);
            __syncthreads();
            if (s_c >= need) pref = trial;
            __syncthreads();
        }
        if (tid == 0) s_thr = pref;
    }
    __syncthreads();

    unsigned thr = s_thr;                 // exact key of k-th largest
    float4* yo4 = (float4*)(y + rowoff);
    #pragma unroll
    for (int q = 0; q < 2; ++q) {
        int t = tid + 512 * q;
        float4 v;
        v.x = (kreg[q * 4 + 0] >= thr) ? vreg[q * 4 + 0] : 0.f;
        v.y = (kreg[q * 4 + 1] >= thr) ? vreg[q * 4 + 1] : 0.f;
        v.z = (kreg[q * 4 + 2] >= thr) ? vreg[q * 4 + 2] : 0.f;
        v.w = (kreg[q * 4 + 3] >= thr) ? vreg[q * 4 + 3] : 0.f;
        yo4[t] = v;
    }
}

// ---------------- launch ----------------
extern "C" void kernel_launch(void* const* d_in, const int* in_sizes, int n_in,
                              void* d_out, int out_size) {
    const float* x    = (const float*)d_in[0];
    const float* W    = (const float*)d_in[1];
    const float* b    = (const float*)d_in[2];
    const float* m    = (const float*)d_in[3];
    const float* duty = (const float*)d_in[4];
    const int*   k    = (const int*)d_in[5];
    float* out = (float*)d_out;

    int B = in_sizes[0] / DIN;   // 16384

    k_prep<<<DOUT / 8, 256>>>(W, m, duty, k);

    const int smem_bytes = (DIN * XPITCH + WARPS * RB * OSP) * (int)sizeof(float)
                         + WARPS * 2 * 32 * (int)sizeof(int4);   // 172KB + 16KB
    cudaFuncSetAttribute(k_gemm, cudaFuncAttributeMaxDynamicSharedMemorySize, smem_bytes);
    dim3 grid(B / RB, DOUT / (WARPS * CPW));   // (256, 4)
    k_gemm<<<grid, 32 * WARPS, smem_bytes>>>(x, b, out);

    k_select<<<B, 512>>>(out, k);
}

// round 15
// speedup vs baseline: 1.6072x; 1.6072x over previous
#include <cuda_runtime.h>
#include <cstdint>

#define DIN   512
#define DOUT  4096
#define CAP   96          // max stored nonzeros per column

#define RB    64          // batch rows per GEMM CTA (2 rows per lane)
#define WARPS 16
#define CPW   64          // columns per warp
#define XPITCH 66         // x-tile pitch (even -> aligned float2, conflict-free)
#define OSP   9           // out-staging pitch

// ---------------- device scratch (static: allocation-free) ----------------
// g_list entries: {byte offset idx*XPITCH*4, fp32 bits of W*mask}, padded to
// even count with exact {0, 0.0f} (adding 0.0 is fp32-exact).
__device__ __align__(16) int2  g_list[DOUT * CAP];
__device__            int      g_nnz[DOUT];
__device__ __align__(16) float g_boost[DOUT];

// ---------------- kernel 1: compact sparse lists + boost ----------------
__global__ void k_prep(const float* __restrict__ W, const float* __restrict__ M,
                       const float* __restrict__ duty, const int* __restrict__ kptr) {
    int gt = blockIdx.x * blockDim.x + threadIdx.x;
    if (gt < DOUT) {
        float target = (float)(*kptr) / (float)DOUT;
        g_boost[gt] = expf(0.5f * (target - duty[gt]));
    }
    int j    = blockIdx.x * (blockDim.x >> 5) + (threadIdx.x >> 5);
    int lane = threadIdx.x & 31;
    if (j >= DOUT) return;
    const float* Wr = W + (size_t)j * DIN;
    const float* Mr = M + (size_t)j * DIN;
    int base = 0;
    for (int c = 0; c < DIN / 32; ++c) {
        int i = c * 32 + lane;
        float w = Wr[i] * Mr[i];                 // mask is exactly 0.0 or 1.0
        bool nz = (w != 0.0f);
        unsigned bal = __ballot_sync(0xffffffffu, nz);
        int pos = base + __popc(bal & ((1u << lane) - 1u));
        if (nz && pos < CAP)
            g_list[j * CAP + pos] = make_int2(i * XPITCH * 4, __float_as_int(w));
        base += __popc(bal);
    }
    if (lane == 0) {
        int n = (base < CAP) ? base : CAP;
        if ((n & 1) && n < CAP) g_list[j * CAP + n] = make_int2(0, 0); // exact pad
        g_nnz[j] = n;
    }
}

// ---------------- kernel 2: sparse gather GEMM (fp32 bit-exact, R9 best) ----
__global__ void __launch_bounds__(32 * WARPS, 1)
k_gemm(const float* __restrict__ x, const float* __restrict__ bias,
       float* __restrict__ yout) {
    extern __shared__ float sm[];
    float* xs  = sm;                       // [DIN][XPITCH] transposed x tile
    float* os  = sm + DIN * XPITCH;        // [WARPS][RB][OSP] out staging
    int4*  stg = (int4*)(os + WARPS * RB * OSP); // [WARPS][2][32] entry pairs
    int tid  = threadIdx.x;
    int w    = tid >> 5;
    int lane = tid & 31;
    int rowbase = blockIdx.x * RB;

    const float4* x4 = (const float4*)(x + (size_t)rowbase * DIN);
    for (int t = tid; t < RB * (DIN / 4); t += blockDim.x) {
        int r  = t >> 7;
        int i4 = t & 127;
        float4 v = x4[(size_t)r * (DIN / 4) + i4];
        int ib = i4 * 4;
        xs[(ib + 0) * XPITCH + r] = v.x;
        xs[(ib + 1) * XPITCH + r] = v.y;
        xs[(ib + 2) * XPITCH + r] = v.z;
        xs[(ib + 3) * XPITCH + r] = v.w;
    }
    __syncthreads();

    float* osw  = os + w * (RB * OSP);
    int jwarp   = blockIdx.y * (WARPS * CPW) + w * CPW;
    const char* xbase = (const char*)xs + lane * 8;
    int2* stgw = (int2*)(stg + w * 64);

    const int2* L;
    L = &g_list[(size_t)jwarp * CAP];
    int2 rA = __ldg(L + lane), rB = __ldg(L + 32 + lane);
    int n_cur = __ldg(&g_nnz[jwarp]);
    stgw[lane] = rA; stgw[32 + lane] = rB;
    L = &g_list[(size_t)(jwarp + 1) * CAP];
    rA = __ldg(L + lane); rB = __ldg(L + 32 + lane);
    int n_nxt = __ldg(&g_nnz[jwarp + 1]);
    __syncwarp();

    for (int ci = 0; ci < CPW; ++ci) {
        int j = jwarp + ci;
        if (ci + 1 < CPW) {
            int2* sb = stgw + ((ci + 1) & 1) * 64;
            sb[lane] = rA; sb[32 + lane] = rB;
        }
        int n_pf = 0;
        if (ci + 2 < CPW) {
            L = &g_list[(size_t)(jwarp + ci + 2) * CAP];
            rA = __ldg(L + lane); rB = __ldg(L + 32 + lane);
            n_pf = __ldg(&g_nnz[jwarp + ci + 2]);
        }

        const int4* sb4 = (const int4*)(stgw + (ci & 1) * 64);
        int nc = (n_cur < 64) ? n_cur : 64;
        int npairs = (nc + 1) >> 1;
        float acc0 = 0.f, acc1 = 0.f;
        #pragma unroll 4
        for (int p = 0; p < npairs; ++p) {
            int4 q = sb4[p];
            float2 xv0 = *(const float2*)(xbase + q.x);
            float2 xv1 = *(const float2*)(xbase + q.z);
            float v0 = __int_as_float(q.y);
            float v1 = __int_as_float(q.w);
            acc0 = fmaf(xv0.x, v0, acc0);
            acc1 = fmaf(xv0.y, v0, acc1);
            acc0 = fmaf(xv1.x, v1, acc0);
            acc1 = fmaf(xv1.y, v1, acc1);
        }
        if (n_cur > 64) {
            for (int e = 64; e < n_cur; ++e) {
                int2 pe = __ldg(&g_list[(size_t)j * CAP + e]);
                float v = __int_as_float(pe.y);
                float2 xv = *(const float2*)(xbase + pe.x);
                acc0 = fmaf(xv.x, v, acc0);
                acc1 = fmaf(xv.y, v, acc1);
            }
        }
        float bj = __ldg(&bias[j]);
        int cc = ci & 7;
        osw[(2 * lane)     * OSP + cc] = acc0 + bj;
        osw[(2 * lane + 1) * OSP + cc] = acc1 + bj;

        n_cur = n_nxt; n_nxt = n_pf;

        if (cc == 7) {
            __syncwarp();
            int j0 = jwarp + (ci & ~7);
            #pragma unroll
            for (int q = 0; q < 4; ++q) {
                int chunk = q * 32 + lane;
                int row   = chunk >> 1;
                int c0    = (chunk & 1) * 4;
                float4 v;
                v.x = osw[row * OSP + c0 + 0];
                v.y = osw[row * OSP + c0 + 1];
                v.z = osw[row * OSP + c0 + 2];
                v.w = osw[row * OSP + c0 + 3];
                *(float4*)&yout[(size_t)(rowbase + row) * DOUT + j0 + c0] = v;
            }
        }
        __syncwarp();
    }
}

// ---------------- kernel 3: radix select (R8 structure, low-reg) ------------
// Values are NOT kept in registers: the rewrite phase re-reads y (L2-hot).
// ~30 regs -> 8 CTAs/SM -> double the rows in flight vs R9 (latency-bound).
__global__ void __launch_bounds__(256)
k_select(float* __restrict__ y, const int* __restrict__ kptr) {
    __shared__ unsigned whist[8 * 256];   // per-warp histograms
    __shared__ unsigned ssum[256];        // suffix sums
    __shared__ unsigned warptot[8];
    __shared__ unsigned s_prefix;
    __shared__ int      s_kk;

    int tid  = threadIdx.x;
    int w    = tid >> 5;
    int lane = tid & 31;
    size_t rowoff = (size_t)blockIdx.x * DOUT;
    const float4* y4 = (const float4*)(y + rowoff);
    const float4* b4 = (const float4*)g_boost;

    unsigned kreg[16];
    #pragma unroll
    for (int q = 0; q < 4; ++q) {
        int t = tid + 256 * q;
        float4 v  = y4[t];
        float4 bo = b4[t];
        float bv[4] = { v.x * bo.x, v.y * bo.y, v.z * bo.z, v.w * bo.w };
        #pragma unroll
        for (int e = 0; e < 4; ++e) {
            unsigned u = __float_as_uint(bv[e]);
            kreg[q * 4 + e] = (u & 0x80000000u) ? ~u : (u | 0x80000000u);
        }
    }
    #pragma unroll
    for (int h = 0; h < 8; ++h) whist[h * 256 + tid] = 0u;
    if (tid == 0) { s_prefix = 0u; s_kk = *kptr; }
    unsigned act = 0xffffu;               // 16-bit active-element mask
    __syncthreads();

    for (int pass = 0; pass < 4; ++pass) {
        int shift = 24 - 8 * pass;
        int kk = s_kk;
        unsigned m = act;
        while (m) {
            int q = __ffs(m) - 1; m &= m - 1;
            atomicAdd(&whist[w * 256 + ((kreg[q] >> shift) & 255)], 1u);
        }
        __syncthreads();
        unsigned h = 0;
        #pragma unroll
        for (int ww = 0; ww < 8; ++ww) h += whist[ww * 256 + tid];
        unsigned v = h;
        #pragma unroll
        for (int off = 1; off < 32; off <<= 1) {
            unsigned o = __shfl_down_sync(0xffffffffu, v, off);
            if (lane + off < 32) v += o;
        }
        if (lane == 0) warptot[w] = v;
        __syncthreads();
        unsigned above = 0;
        #pragma unroll
        for (int ww = 0; ww < 8; ++ww) if (ww > w) above += warptot[ww];
        unsigned S = v + above;           // sum of h over bins >= tid
        ssum[tid] = S;
        #pragma unroll
        for (int hh = 0; hh < 8; ++hh) whist[hh * 256 + tid] = 0u; // re-zero
        __syncthreads();
        unsigned Snext = (tid == 255) ? 0u : ssum[tid + 1];
        if (S >= (unsigned)kk && Snext < (unsigned)kk) {   // exactly one thread
            s_prefix |= ((unsigned)tid) << shift;
            s_kk = kk - (int)Snext;
        }
        __syncthreads();
        unsigned pb = (s_prefix >> shift) & 255u;
        unsigned m2 = act; act = 0u;
        while (m2) {
            int q = __ffs(m2) - 1; m2 &= m2 - 1;
            if (((kreg[q] >> shift) & 255u) == pb) act |= 1u << q;
        }
    }

    unsigned thr = s_prefix;              // exact key of kth largest
    float4* yo4 = (float4*)(y + rowoff);
    #pragma unroll
    for (int q = 0; q < 4; ++q) {
        int t = tid + 256 * q;
        float4 v = y4[t];                 // re-read original y (L2-hot)
        v.x = (kreg[q * 4 + 0] >= thr) ? v.x : 0.f;
        v.y = (kreg[q * 4 + 1] >= thr) ? v.y : 0.f;
        v.z = (kreg[q * 4 + 2] >= thr) ? v.z : 0.f;
        v.w = (kreg[q * 4 + 3] >= thr) ? v.w : 0.f;
        __stwt(&yo4[t], v);               // streaming: y never re-read
    }
}

// ---------------- launch ----------------
extern "C" void kernel_launch(void* const* d_in, const int* in_sizes, int n_in,
                              void* d_out, int out_size) {
    const float* x    = (const float*)d_in[0];
    const float* W    = (const float*)d_in[1];
    const float* b    = (const float*)d_in[2];
    const float* m    = (const float*)d_in[3];
    const float* duty = (const float*)d_in[4];
    const int*   k    = (const int*)d_in[5];
    float* out = (float*)d_out;

    int B = in_sizes[0] / DIN;   // 16384

    k_prep<<<DOUT / 8, 256>>>(W, m, duty, k);

    const int smem_bytes = (DIN * XPITCH + WARPS * RB * OSP) * (int)sizeof(float)
                         + WARPS * 2 * 32 * (int)sizeof(int4);   // 172KB + 16KB
    cudaFuncSetAttribute(k_gemm, cudaFuncAttributeMaxDynamicSharedMemorySize, smem_bytes);
    dim3 grid(B / RB, DOUT / (WARPS * CPW));   // (256, 4)
    k_gemm<<<grid, 32 * WARPS, smem_bytes>>>(x, b, out);

    k_select<<<B, 256>>>(out, k);
}